// round 2
// baseline (speedup 1.0000x reference)
#include <cuda_runtime.h>
#include <math.h>

#define BB 4096
#define INF 1024
#define HH 1024
#define NG 5120           // 5 gates * 1024
#define BH (4096*1024)

// ---------------- scratch (static device globals; no allocs) ----------------
__device__ float g_gates[(size_t)BB * NG];   // activated gates [B, 5*H]  (80 MB)
__device__ float g_ah[(size_t)BB * HH];      // alpha hidden
__device__ float g_alpha[BB];                // alpha_t [B]
__device__ float g_r1[(size_t)BB * HH];
__device__ float g_r2[(size_t)BB * HH];

__device__ __forceinline__ float sigmoidf_fast(float v) {
    return 1.f / (1.f + __expf(-v));
}

// ---------------- generic dual-operand SGEMM ----------------
// C[M,N] = epilogue( A1@W1^T [+ A2@W2^T] + b1 [+ b2] )
// A row-major [M,K] pitch=K ; W row-major [N,K] pitch=ldw
// MODE: 0=none, 1=relu, 2=gate activations (col/1024==3 -> tanh else sigmoid),
//       3=final LSTM cell epilogue (writes out_h, out_c; C unused)
template<int MODE, int DUAL>
__global__ __launch_bounds__(256, 2)
void gemm_kernel(const float* __restrict__ A1, const float* __restrict__ W1, int ldw1, int K1,
                 const float* __restrict__ A2, const float* __restrict__ W2, int ldw2, int K2,
                 const float* __restrict__ b1, const float* __restrict__ b2,
                 float* __restrict__ C, int N,
                 const float* __restrict__ gates, const float* __restrict__ c_prev,
                 const float* __restrict__ alpha, const float* __restrict__ ssg,
                 float* __restrict__ out_h, float* __restrict__ out_c)
{
    __shared__ float As[16][128];
    __shared__ float Ws[16][128];

    const int tid = threadIdx.x;
    const int tx = tid & 15;         // 0..15 -> N sub-tile
    const int ty = tid >> 4;         // 0..15 -> M sub-tile
    const int m0 = blockIdx.y * 128;
    const int n0 = blockIdx.x * 128;

    const int lrow = tid >> 1;       // 0..127 row within tile to load
    const int lcol = (tid & 1) * 8;  // 0 or 8

    float acc[8][8];
#pragma unroll
    for (int i = 0; i < 8; ++i)
#pragma unroll
        for (int j = 0; j < 8; ++j) acc[i][j] = 0.f;

#pragma unroll
    for (int pair = 0; pair < (DUAL ? 2 : 1); ++pair) {
        const float* A  = pair ? A2 : A1;
        const float* W  = pair ? W2 : W1;
        const int ldw   = pair ? ldw2 : ldw1;
        const int K     = pair ? K2 : K1;

        const float* ag = A + (size_t)(m0 + lrow) * K + lcol;
        const float* wg = W + (size_t)(n0 + lrow) * ldw + lcol;

        for (int kb = 0; kb < K; kb += 16) {
            float4 a0 = *(const float4*)(ag + kb);
            float4 a1 = *(const float4*)(ag + kb + 4);
            float4 w0 = *(const float4*)(wg + kb);
            float4 w1 = *(const float4*)(wg + kb + 4);

            As[lcol + 0][lrow] = a0.x; As[lcol + 1][lrow] = a0.y;
            As[lcol + 2][lrow] = a0.z; As[lcol + 3][lrow] = a0.w;
            As[lcol + 4][lrow] = a1.x; As[lcol + 5][lrow] = a1.y;
            As[lcol + 6][lrow] = a1.z; As[lcol + 7][lrow] = a1.w;
            Ws[lcol + 0][lrow] = w0.x; Ws[lcol + 1][lrow] = w0.y;
            Ws[lcol + 2][lrow] = w0.z; Ws[lcol + 3][lrow] = w0.w;
            Ws[lcol + 4][lrow] = w1.x; Ws[lcol + 5][lrow] = w1.y;
            Ws[lcol + 6][lrow] = w1.z; Ws[lcol + 7][lrow] = w1.w;
            __syncthreads();

#pragma unroll
            for (int kk = 0; kk < 16; ++kk) {
                float a[8], b[8];
                *(float4*)(&a[0]) = *(const float4*)(&As[kk][ty * 8]);
                *(float4*)(&a[4]) = *(const float4*)(&As[kk][ty * 8 + 4]);
                *(float4*)(&b[0]) = *(const float4*)(&Ws[kk][tx * 8]);
                *(float4*)(&b[4]) = *(const float4*)(&Ws[kk][tx * 8 + 4]);
#pragma unroll
                for (int i = 0; i < 8; ++i)
#pragma unroll
                    for (int j = 0; j < 8; ++j)
                        acc[i][j] = fmaf(a[i], b[j], acc[i][j]);
            }
            __syncthreads();
        }
    }

    // ------------- epilogue -------------
#pragma unroll
    for (int i = 0; i < 8; ++i) {
        const int m = m0 + ty * 8 + i;
#pragma unroll
        for (int j = 0; j < 8; ++j) {
            const int n = n0 + tx * 8 + j;
            float v = acc[i][j];
            v += b1[n];
            if (DUAL && b2) v += b2[n];
            if (MODE == 1) {
                v = fmaxf(v, 0.f);
                C[(size_t)m * N + n] = v;
            } else if (MODE == 2) {
                const int g = n >> 10;
                v = (g == 3) ? tanhf(v) : sigmoidf_fast(v);
                C[(size_t)m * N + n] = v;
            } else if (MODE == 3) {
                const size_t gbase = (size_t)m * NG + n;
                const float it = gates[gbase];
                const float ft = gates[gbase + 1024];
                const float ot = gates[gbase + 2048];
                const float ch = gates[gbase + 3072];
                const float st = gates[gbase + 4096];
                const size_t idx = (size_t)m * HH + n;
                const float c = ft * c_prev[idx]
                              + it * ch * st * alpha[m] * ssg[idx]
                              + v;                         // v = residual
                out_c[idx] = c;
                out_h[idx] = ot * tanhf(c);
            } else {
                C[(size_t)m * N + n] = v;
            }
        }
    }
}

// ---------------- alpha: sigmoid(ah @ a2_w^T + a2_b), N=1 ----------------
__global__ __launch_bounds__(256)
void alpha_kernel(const float* __restrict__ ah,
                  const float* __restrict__ a2w,
                  const float* __restrict__ a2b,
                  float* __restrict__ alpha)
{
    const int m = blockIdx.x;
    const int t = threadIdx.x;        // 256 threads
    float s = 0.f;
#pragma unroll
    for (int k = t; k < 1024; k += 256)
        s += ah[(size_t)m * 1024 + k] * a2w[k];
    for (int o = 16; o; o >>= 1) s += __shfl_down_sync(0xffffffffu, s, o);
    __shared__ float red[8];
    if ((t & 31) == 0) red[t >> 5] = s;
    __syncthreads();
    if (t == 0) {
        float tot = 0.f;
#pragma unroll
        for (int i = 0; i < 8; ++i) tot += red[i];
        alpha[m] = 1.f / (1.f + __expf(-(tot + a2b[0])));
    }
}

// ---------------- launch ----------------
extern "C" void kernel_launch(void* const* d_in, const int* in_sizes, int n_in,
                              void* d_out, int out_size)
{
    const float* x      = (const float*)d_in[0];
    const float* h_prev = (const float*)d_in[1];
    const float* c_prev = (const float*)d_in[2];
    const float* ssg_st = (const float*)d_in[3];
    const float* Wx     = (const float*)d_in[4];   // [5,1024,1024] -> [5120,1024]
    const float* bWx    = (const float*)d_in[5];   // [5120]
    const float* Ux     = (const float*)d_in[6];
    const float* bUx    = (const float*)d_in[7];
    const float* a1_w   = (const float*)d_in[8];   // [1024, 2048]
    const float* a1_b   = (const float*)d_in[9];
    const float* a2_w   = (const float*)d_in[10];  // [1, 1024]
    const float* a2_b   = (const float*)d_in[11];
    const float* r1_w   = (const float*)d_in[12];
    const float* r1_b   = (const float*)d_in[13];
    const float* r2_w   = (const float*)d_in[14];
    const float* r2_b   = (const float*)d_in[15];
    const float* r3_w   = (const float*)d_in[16];
    const float* r3_b   = (const float*)d_in[17];
    const float* ssg_w  = (const float*)d_in[18];
    const float* ssg_b  = (const float*)d_in[19];

    float* out = (float*)d_out;
    float* out_h   = out;                   // [B,H]
    float* out_c   = out + (size_t)BH;      // [B,H]
    float* out_ssg = out + 2 * (size_t)BH;  // [B,H]

    float *gates, *ah, *alpha, *r1, *r2;
    cudaGetSymbolAddress((void**)&gates, g_gates);
    cudaGetSymbolAddress((void**)&ah,    g_ah);
    cudaGetSymbolAddress((void**)&alpha, g_alpha);
    cudaGetSymbolAddress((void**)&r1,    g_r1);
    cudaGetSymbolAddress((void**)&r2,    g_r2);

    const dim3 blk(256);
    const dim3 grid_g(NG / 128, BB / 128);   // 40 x 32
    const dim3 grid_h(HH / 128, BB / 128);   // 8 x 32

    // 1. gates = act( x@Wx^T + h@Ux^T + bWx + bUx )   [B, 5120]
    gemm_kernel<2,1><<<grid_g, blk>>>(x, Wx, 1024, 1024, h_prev, Ux, 1024, 1024,
                                      bWx, bUx, gates, NG,
                                      nullptr, nullptr, nullptr, nullptr, nullptr, nullptr);
    // 2. alpha hidden = relu( x@a1_w[:, :1024]^T + h@a1_w[:, 1024:]^T + a1_b )
    gemm_kernel<1,1><<<grid_h, blk>>>(x, a1_w, 2048, 1024, h_prev, a1_w + 1024, 2048, 1024,
                                      a1_b, nullptr, ah, HH,
                                      nullptr, nullptr, nullptr, nullptr, nullptr, nullptr);
    // 3. alpha = sigmoid(ah @ a2_w^T + a2_b)
    alpha_kernel<<<BB, blk>>>(ah, a2_w, a2_b, alpha);
    // 4. ssg_new = (ssg + h)@ssg_w^T + ssg_b = ssg@W^T + h@W^T + b  -> out[2BH:]
    gemm_kernel<0,1><<<grid_h, blk>>>(ssg_st, ssg_w, 1024, 1024, h_prev, ssg_w, 1024, 1024,
                                      ssg_b, nullptr, out_ssg, HH,
                                      nullptr, nullptr, nullptr, nullptr, nullptr, nullptr);
    // 5. r1 = relu(h@r1_w^T + r1_b)
    gemm_kernel<1,0><<<grid_h, blk>>>(h_prev, r1_w, 1024, 1024, nullptr, nullptr, 0, 0,
                                      r1_b, nullptr, r1, HH,
                                      nullptr, nullptr, nullptr, nullptr, nullptr, nullptr);
    // 6. r2 = relu(r1@r2_w^T + r2_b)
    gemm_kernel<1,0><<<grid_h, blk>>>(r1, r2_w, 1024, 1024, nullptr, nullptr, 0, 0,
                                      r2_b, nullptr, r2, HH,
                                      nullptr, nullptr, nullptr, nullptr, nullptr, nullptr);
    // 7. residual = r2@r3_w^T + r3_b, fused LSTM cell epilogue -> out_h, out_c
    gemm_kernel<3,0><<<grid_h, blk>>>(r2, r3_w, 1024, 1024, nullptr, nullptr, 0, 0,
                                      r3_b, nullptr, out_c /*unused*/, HH,
                                      gates, c_prev, alpha, out_ssg, out_h, out_c);
}

// round 4
// speedup vs baseline: 2.7317x; 2.7317x over previous
#include <cuda_runtime.h>
#include <cuda_bf16.h>
#include <math.h>
#include <stdint.h>

#define BB 4096
#define HH 1024
#define NG 5120
#define BH (4096*1024)

#define RS 40                        // padded smem row stride (bf16 elems) = 80B
#define ARR_BYTES (128*RS*2)         // 10240 per tile array
#define STG_BYTES (4*ARR_BYTES)      // 40960 per stage (Ah,Al,Wh,Wl)
#define SMEM_BYTES (2*STG_BYTES)     // 81920 double-buffered

// ---------------- scratch (device globals; no allocs) ----------------
__device__ __nv_bfloat16 s_x_hi[(size_t)BB*HH],  s_x_lo[(size_t)BB*HH];
__device__ __nv_bfloat16 s_h_hi[(size_t)BB*HH],  s_h_lo[(size_t)BB*HH];
__device__ __nv_bfloat16 s_sg_hi[(size_t)BB*HH], s_sg_lo[(size_t)BB*HH];  // ssg_state + h_prev
__device__ __nv_bfloat16 s_r1_hi[(size_t)BB*HH], s_r1_lo[(size_t)BB*HH];
__device__ __nv_bfloat16 s_r2_hi[(size_t)BB*HH], s_r2_lo[(size_t)BB*HH];
__device__ __nv_bfloat16 w_Wx_hi[(size_t)NG*HH], w_Wx_lo[(size_t)NG*HH];
__device__ __nv_bfloat16 w_Ux_hi[(size_t)NG*HH], w_Ux_lo[(size_t)NG*HH];
__device__ __nv_bfloat16 w_a1_hi[(size_t)HH*2048], w_a1_lo[(size_t)HH*2048];
__device__ __nv_bfloat16 w_sw_hi[(size_t)HH*HH], w_sw_lo[(size_t)HH*HH];
__device__ __nv_bfloat16 w_r1_hi[(size_t)HH*HH], w_r1_lo[(size_t)HH*HH];
__device__ __nv_bfloat16 w_r2_hi[(size_t)HH*HH], w_r2_lo[(size_t)HH*HH];
__device__ __nv_bfloat16 w_r3_hi[(size_t)HH*HH], w_r3_lo[(size_t)HH*HH];
__device__ float g_gates[(size_t)BB*NG];
__device__ float g_ah[(size_t)BB*HH];
__device__ float g_res[(size_t)BB*HH];
__device__ float g_alpha[BB];

// ---------------- helpers ----------------
__device__ __forceinline__ uint32_t smem_u32(const void* p) {
    uint32_t a;
    asm("{ .reg .u64 t; cvta.to.shared.u64 t, %1; cvt.u32.u64 %0, t; }" : "=r"(a) : "l"(p));
    return a;
}
__device__ __forceinline__ void ldsm4(uint32_t& r0, uint32_t& r1, uint32_t& r2, uint32_t& r3, uint32_t a) {
    asm volatile("ldmatrix.sync.aligned.m8n8.x4.shared.b16 {%0,%1,%2,%3}, [%4];"
        : "=r"(r0), "=r"(r1), "=r"(r2), "=r"(r3) : "r"(a));
}
__device__ __forceinline__ void ldsm2(uint32_t& r0, uint32_t& r1, uint32_t a) {
    asm volatile("ldmatrix.sync.aligned.m8n8.x2.shared.b16 {%0,%1}, [%2];"
        : "=r"(r0), "=r"(r1) : "r"(a));
}
__device__ __forceinline__ void mma16816(float* c, const uint32_t* a, const uint32_t* b) {
    asm volatile("mma.sync.aligned.m16n8k16.row.col.f32.bf16.bf16.f32 "
        "{%0,%1,%2,%3}, {%4,%5,%6,%7}, {%8,%9}, {%0,%1,%2,%3};"
        : "+f"(c[0]), "+f"(c[1]), "+f"(c[2]), "+f"(c[3])
        : "r"(a[0]), "r"(a[1]), "r"(a[2]), "r"(a[3]), "r"(b[0]), "r"(b[1]));
}
#define CP_ASYNC16(dst, src) \
    asm volatile("cp.async.cg.shared.global [%0], [%1], 16;" :: "r"(dst), "l"(src))
#define CP_COMMIT()  asm volatile("cp.async.commit_group;" ::: "memory")
#define CP_WAIT(n)   asm volatile("cp.async.wait_group %0;" :: "n"(n) : "memory")

// ---------------- conversion kernels ----------------
__global__ void cvt_split(const float4* __restrict__ in,
                          __nv_bfloat162* __restrict__ hi, __nv_bfloat162* __restrict__ lo, int n4)
{
    int i = blockIdx.x * 256 + threadIdx.x;
    if (i >= n4) return;
    float4 v = in[i];
    __nv_bfloat16 h0 = __float2bfloat16_rn(v.x), h1 = __float2bfloat16_rn(v.y);
    __nv_bfloat16 h2 = __float2bfloat16_rn(v.z), h3 = __float2bfloat16_rn(v.w);
    __nv_bfloat16 l0 = __float2bfloat16_rn(v.x - __bfloat162float(h0));
    __nv_bfloat16 l1 = __float2bfloat16_rn(v.y - __bfloat162float(h1));
    __nv_bfloat16 l2 = __float2bfloat16_rn(v.z - __bfloat162float(h2));
    __nv_bfloat16 l3 = __float2bfloat16_rn(v.w - __bfloat162float(h3));
    hi[2*i]   = __nv_bfloat162(h0, h1); hi[2*i+1] = __nv_bfloat162(h2, h3);
    lo[2*i]   = __nv_bfloat162(l0, l1); lo[2*i+1] = __nv_bfloat162(l2, l3);
}
__global__ void cvt_split_add(const float4* __restrict__ a, const float4* __restrict__ b,
                              __nv_bfloat162* __restrict__ hi, __nv_bfloat162* __restrict__ lo, int n4)
{
    int i = blockIdx.x * 256 + threadIdx.x;
    if (i >= n4) return;
    float4 va = a[i], vb = b[i];
    float x0 = va.x + vb.x, x1 = va.y + vb.y, x2 = va.z + vb.z, x3 = va.w + vb.w;
    __nv_bfloat16 h0 = __float2bfloat16_rn(x0), h1 = __float2bfloat16_rn(x1);
    __nv_bfloat16 h2 = __float2bfloat16_rn(x2), h3 = __float2bfloat16_rn(x3);
    __nv_bfloat16 l0 = __float2bfloat16_rn(x0 - __bfloat162float(h0));
    __nv_bfloat16 l1 = __float2bfloat16_rn(x1 - __bfloat162float(h1));
    __nv_bfloat16 l2 = __float2bfloat16_rn(x2 - __bfloat162float(h2));
    __nv_bfloat16 l3 = __float2bfloat16_rn(x3 - __bfloat162float(h3));
    hi[2*i]   = __nv_bfloat162(h0, h1); hi[2*i+1] = __nv_bfloat162(h2, h3);
    lo[2*i]   = __nv_bfloat162(l0, l1); lo[2*i+1] = __nv_bfloat162(l2, l3);
}

// ---------------- bf16-split mma.sync GEMM ----------------
// C[M,N] = epi( A1@W1^T [+ A2@W2^T] + b1 [+ b2] ) ; operands as bf16 hi/lo pairs
// CTA tile 128x128, K-step 32, 8 warps (2x4), warp tile 64x32.
// MODE: 0 = fp32 out ; 1 = relu fp32 ; 2 = gate activations ; 4 = relu + bf16 hi/lo out
template<int MODE>
__global__ void __launch_bounds__(256, 2)
mma_gemm(const __nv_bfloat16* __restrict__ A1h, const __nv_bfloat16* __restrict__ A1l, int lda1,
         const __nv_bfloat16* __restrict__ W1h, const __nv_bfloat16* __restrict__ W1l, int ldw1, int s1,
         const __nv_bfloat16* __restrict__ A2h, const __nv_bfloat16* __restrict__ A2l, int lda2,
         const __nv_bfloat16* __restrict__ W2h, const __nv_bfloat16* __restrict__ W2l, int ldw2, int s2,
         const float* __restrict__ b1, const float* __restrict__ b2,
         float* __restrict__ Cf, __nv_bfloat16* __restrict__ Chi, __nv_bfloat16* __restrict__ Clo,
         int ldc)
{
    extern __shared__ char smem[];
    const uint32_t sbase = smem_u32(smem);
    const int tid = threadIdx.x, wid = tid >> 5, lane = tid & 31;
    const int wm = wid >> 2, wn = wid & 3;            // 2 x 4 warp grid
    const int m0 = blockIdx.y * 128, n0 = blockIdx.x * 128;
    const int S = s1 + s2;

    float acc[4][4][4];
#pragma unroll
    for (int a = 0; a < 4; ++a)
#pragma unroll
        for (int b = 0; b < 4; ++b)
#pragma unroll
            for (int q = 0; q < 4; ++q) acc[a][b][q] = 0.f;

    auto issue_load = [&](int s) {
        const __nv_bfloat16 *Ah, *Al, *Wh, *Wl; int lda, ldw, koff;
        if (s < s1) { Ah = A1h; Al = A1l; Wh = W1h; Wl = W1l; lda = lda1; ldw = ldw1; koff = s * 32; }
        else        { Ah = A2h; Al = A2l; Wh = W2h; Wl = W2l; lda = lda2; ldw = ldw2; koff = (s - s1) * 32; }
        const __nv_bfloat16* srcs[4] = {Ah, Al, Wh, Wl};
        uint32_t dst0 = sbase + (uint32_t)(s & 1) * STG_BYTES;
#pragma unroll
        for (int arr = 0; arr < 4; ++arr) {
            const __nv_bfloat16* src = srcs[arr];
            int ldx = (arr < 2) ? lda : ldw;
            int rb  = (arr < 2) ? m0  : n0;
#pragma unroll
            for (int i = 0; i < 2; ++i) {
                int idx = tid + i * 256;           // 512 16B chunks per array
                int row = idx >> 2, c = idx & 3;
                const __nv_bfloat16* g = src + (size_t)(rb + row) * ldx + koff + c * 8;
                uint32_t d = dst0 + arr * ARR_BYTES + row * 80 + c * 16;
                CP_ASYNC16(d, g);
            }
        }
        CP_COMMIT();
    };

    issue_load(0);

    for (int s = 0; s < S; ++s) {
        if (s + 1 < S) { issue_load(s + 1); CP_WAIT(1); }
        else           { CP_WAIT(0); }
        __syncthreads();

        uint32_t base = sbase + (uint32_t)(s & 1) * STG_BYTES;
        uint32_t Ahb = base, Alb = base + ARR_BYTES;
        uint32_t Whb = base + 2 * ARR_BYTES, Wlb = base + 3 * ARR_BYTES;

#pragma unroll
        for (int k16 = 0; k16 < 2; ++k16) {
            const int k0 = k16 * 16;
            uint32_t bh[4][2], bl[4][2];
            const int brow = wn * 32 + (lane & 7);
            const int bcol = k0 + ((lane >> 3) & 1) * 8;
#pragma unroll
            for (int nb = 0; nb < 4; ++nb) {
                uint32_t off = (uint32_t)((brow + nb * 8) * RS + bcol) * 2;
                ldsm2(bh[nb][0], bh[nb][1], Whb + off);
                ldsm2(bl[nb][0], bl[nb][1], Wlb + off);
            }
            const int arow = wm * 64 + (lane & 15);
            const int acol = k0 + (lane >> 4) * 8;
#pragma unroll
            for (int mb = 0; mb < 4; ++mb) {
                uint32_t ah[4], al[4];
                uint32_t off = (uint32_t)((arow + mb * 16) * RS + acol) * 2;
                ldsm4(ah[0], ah[1], ah[2], ah[3], Ahb + off);
                ldsm4(al[0], al[1], al[2], al[3], Alb + off);
#pragma unroll
                for (int nb = 0; nb < 4; ++nb) {
                    mma16816(acc[mb][nb], ah, bh[nb]);
                    mma16816(acc[mb][nb], ah, bl[nb]);
                    mma16816(acc[mb][nb], al, bh[nb]);
                }
            }
        }
        __syncthreads();
    }

    // ---------------- epilogue ----------------
#pragma unroll
    for (int mb = 0; mb < 4; ++mb) {
#pragma unroll
        for (int nb = 0; nb < 4; ++nb) {
#pragma unroll
            for (int h = 0; h < 2; ++h) {
                const int m = m0 + wm * 64 + mb * 16 + (lane >> 2) + h * 8;
                const int n = n0 + wn * 32 + nb * 8 + 2 * (lane & 3);
                float v0 = acc[mb][nb][2 * h]     + b1[n];
                float v1 = acc[mb][nb][2 * h + 1] + b1[n + 1];
                if (b2) { v0 += b2[n]; v1 += b2[n + 1]; }
                if (MODE == 1 || MODE == 4) { v0 = fmaxf(v0, 0.f); v1 = fmaxf(v1, 0.f); }
                if (MODE == 2) {
                    const int g = n >> 10;   // both cols in same gate (n even)
                    if (g == 3) { v0 = tanhf(v0); v1 = tanhf(v1); }
                    else { v0 = 1.f / (1.f + __expf(-v0)); v1 = 1.f / (1.f + __expf(-v1)); }
                }
                const size_t gm = (size_t)m * ldc + n;
                if (MODE == 4) {
                    __nv_bfloat16 h0 = __float2bfloat16_rn(v0), h1 = __float2bfloat16_rn(v1);
                    __nv_bfloat16 l0 = __float2bfloat16_rn(v0 - __bfloat162float(h0));
                    __nv_bfloat16 l1 = __float2bfloat16_rn(v1 - __bfloat162float(h1));
                    *(__nv_bfloat162*)(Chi + gm) = __nv_bfloat162(h0, h1);
                    *(__nv_bfloat162*)(Clo + gm) = __nv_bfloat162(l0, l1);
                } else {
                    float2 o; o.x = v0; o.y = v1;
                    *(float2*)(Cf + gm) = o;
                }
            }
        }
    }
}

// ---------------- alpha: sigmoid(ah @ a2_w^T + a2_b) ----------------
__global__ void __launch_bounds__(256)
alpha_kernel(const float* __restrict__ ah, const float* __restrict__ a2w,
             const float* __restrict__ a2b, float* __restrict__ alpha)
{
    const int m = blockIdx.x;
    const int t = threadIdx.x;
    float s = 0.f;
#pragma unroll
    for (int k = t; k < 1024; k += 256)
        s += ah[(size_t)m * 1024 + k] * a2w[k];
    for (int o = 16; o; o >>= 1) s += __shfl_down_sync(0xffffffffu, s, o);
    __shared__ float red[8];
    if ((t & 31) == 0) red[t >> 5] = s;
    __syncthreads();
    if (t == 0) {
        float tot = 0.f;
#pragma unroll
        for (int i = 0; i < 8; ++i) tot += red[i];
        alpha[m] = 1.f / (1.f + __expf(-(tot + a2b[0])));
    }
}

// ---------------- fused cell update ----------------
__global__ void __launch_bounds__(256)
final_cell(const float* __restrict__ gates, const float* __restrict__ c_prev,
           const float* __restrict__ alpha, const float* __restrict__ ssg,
           const float* __restrict__ res, float* __restrict__ out_h, float* __restrict__ out_c)
{
    int i4 = blockIdx.x * 256 + threadIdx.x;       // over BH/4
    int m = i4 >> 8;
    int n = (i4 & 255) * 4;
    const float* gb = gates + (size_t)m * NG + n;
    float4 it = *(const float4*)(gb);
    float4 ft = *(const float4*)(gb + 1024);
    float4 ot = *(const float4*)(gb + 2048);
    float4 ch = *(const float4*)(gb + 3072);
    float4 st = *(const float4*)(gb + 4096);
    float a = alpha[m];
    float4 cp = *(const float4*)(c_prev + (size_t)i4 * 4);
    float4 sg = *(const float4*)(ssg + (size_t)i4 * 4);
    float4 rs = *(const float4*)(res + (size_t)i4 * 4);
    float4 c, h;
    c.x = ft.x * cp.x + it.x * ch.x * st.x * a * sg.x + rs.x;
    c.y = ft.y * cp.y + it.y * ch.y * st.y * a * sg.y + rs.y;
    c.z = ft.z * cp.z + it.z * ch.z * st.z * a * sg.z + rs.z;
    c.w = ft.w * cp.w + it.w * ch.w * st.w * a * sg.w + rs.w;
    h.x = ot.x * tanhf(c.x); h.y = ot.y * tanhf(c.y);
    h.z = ot.z * tanhf(c.z); h.w = ot.w * tanhf(c.w);
    *(float4*)(out_c + (size_t)i4 * 4) = c;
    *(float4*)(out_h + (size_t)i4 * 4) = h;
}

// ---------------- launch ----------------
extern "C" void kernel_launch(void* const* d_in, const int* in_sizes, int n_in,
                              void* d_out, int out_size)
{
    const float* x      = (const float*)d_in[0];
    const float* h_prev = (const float*)d_in[1];
    const float* c_prev = (const float*)d_in[2];
    const float* ssg_st = (const float*)d_in[3];
    const float* Wx     = (const float*)d_in[4];
    const float* bWx    = (const float*)d_in[5];
    const float* Ux     = (const float*)d_in[6];
    const float* bUx    = (const float*)d_in[7];
    const float* a1_w   = (const float*)d_in[8];
    const float* a1_b   = (const float*)d_in[9];
    const float* a2_w   = (const float*)d_in[10];
    const float* a2_b   = (const float*)d_in[11];
    const float* r1_w   = (const float*)d_in[12];
    const float* r1_b   = (const float*)d_in[13];
    const float* r2_w   = (const float*)d_in[14];
    const float* r2_b   = (const float*)d_in[15];
    const float* r3_w   = (const float*)d_in[16];
    const float* r3_b   = (const float*)d_in[17];
    const float* ssg_w  = (const float*)d_in[18];
    const float* ssg_b  = (const float*)d_in[19];

    float* out = (float*)d_out;
    float* out_h   = out;
    float* out_c   = out + (size_t)BH;
    float* out_ssg = out + 2 * (size_t)BH;

    __nv_bfloat16 *xh, *xl, *hh, *hl, *sgh, *sgl, *r1h, *r1l, *r2h, *r2l;
    __nv_bfloat16 *Wxh, *Wxl, *Uxh, *Uxl, *a1h, *a1l, *swh, *swl, *w1h, *w1l, *w2h, *w2l, *w3h, *w3l;
    float *gates, *ah, *res, *alpha;
    cudaGetSymbolAddress((void**)&xh, s_x_hi);   cudaGetSymbolAddress((void**)&xl, s_x_lo);
    cudaGetSymbolAddress((void**)&hh, s_h_hi);   cudaGetSymbolAddress((void**)&hl, s_h_lo);
    cudaGetSymbolAddress((void**)&sgh, s_sg_hi); cudaGetSymbolAddress((void**)&sgl, s_sg_lo);
    cudaGetSymbolAddress((void**)&r1h, s_r1_hi); cudaGetSymbolAddress((void**)&r1l, s_r1_lo);
    cudaGetSymbolAddress((void**)&r2h, s_r2_hi); cudaGetSymbolAddress((void**)&r2l, s_r2_lo);
    cudaGetSymbolAddress((void**)&Wxh, w_Wx_hi); cudaGetSymbolAddress((void**)&Wxl, w_Wx_lo);
    cudaGetSymbolAddress((void**)&Uxh, w_Ux_hi); cudaGetSymbolAddress((void**)&Uxl, w_Ux_lo);
    cudaGetSymbolAddress((void**)&a1h, w_a1_hi); cudaGetSymbolAddress((void**)&a1l, w_a1_lo);
    cudaGetSymbolAddress((void**)&swh, w_sw_hi); cudaGetSymbolAddress((void**)&swl, w_sw_lo);
    cudaGetSymbolAddress((void**)&w1h, w_r1_hi); cudaGetSymbolAddress((void**)&w1l, w_r1_lo);
    cudaGetSymbolAddress((void**)&w2h, w_r2_hi); cudaGetSymbolAddress((void**)&w2l, w_r2_lo);
    cudaGetSymbolAddress((void**)&w3h, w_r3_hi); cudaGetSymbolAddress((void**)&w3l, w_r3_lo);
    cudaGetSymbolAddress((void**)&gates, g_gates);
    cudaGetSymbolAddress((void**)&ah, g_ah);
    cudaGetSymbolAddress((void**)&res, g_res);
    cudaGetSymbolAddress((void**)&alpha, g_alpha);

    cudaFuncSetAttribute(mma_gemm<0>, cudaFuncAttributeMaxDynamicSharedMemorySize, SMEM_BYTES);
    cudaFuncSetAttribute(mma_gemm<1>, cudaFuncAttributeMaxDynamicSharedMemorySize, SMEM_BYTES);
    cudaFuncSetAttribute(mma_gemm<2>, cudaFuncAttributeMaxDynamicSharedMemorySize, SMEM_BYTES);
    cudaFuncSetAttribute(mma_gemm<4>, cudaFuncAttributeMaxDynamicSharedMemorySize, SMEM_BYTES);

    const dim3 blk(256);
    auto nblk = [](size_t n) { return (unsigned)((n / 4 + 255) / 256); };

    // ---- conversions ----
    cvt_split<<<nblk((size_t)BB*HH), blk>>>((const float4*)x, (__nv_bfloat162*)xh, (__nv_bfloat162*)xl, BB*HH/4);
    cvt_split<<<nblk((size_t)BB*HH), blk>>>((const float4*)h_prev, (__nv_bfloat162*)hh, (__nv_bfloat162*)hl, BB*HH/4);
    cvt_split_add<<<nblk((size_t)BB*HH), blk>>>((const float4*)ssg_st, (const float4*)h_prev,
                                                (__nv_bfloat162*)sgh, (__nv_bfloat162*)sgl, BB*HH/4);
    cvt_split<<<nblk((size_t)NG*HH), blk>>>((const float4*)Wx, (__nv_bfloat162*)Wxh, (__nv_bfloat162*)Wxl, NG*HH/4);
    cvt_split<<<nblk((size_t)NG*HH), blk>>>((const float4*)Ux, (__nv_bfloat162*)Uxh, (__nv_bfloat162*)Uxl, NG*HH/4);
    cvt_split<<<nblk((size_t)HH*2048), blk>>>((const float4*)a1_w, (__nv_bfloat162*)a1h, (__nv_bfloat162*)a1l, HH*2048/4);
    cvt_split<<<nblk((size_t)HH*HH), blk>>>((const float4*)ssg_w, (__nv_bfloat162*)swh, (__nv_bfloat162*)swl, HH*HH/4);
    cvt_split<<<nblk((size_t)HH*HH), blk>>>((const float4*)r1_w, (__nv_bfloat162*)w1h, (__nv_bfloat162*)w1l, HH*HH/4);
    cvt_split<<<nblk((size_t)HH*HH), blk>>>((const float4*)r2_w, (__nv_bfloat162*)w2h, (__nv_bfloat162*)w2l, HH*HH/4);
    cvt_split<<<nblk((size_t)HH*HH), blk>>>((const float4*)r3_w, (__nv_bfloat162*)w3h, (__nv_bfloat162*)w3l, HH*HH/4);

    const dim3 grid_g(NG / 128, BB / 128);   // 40 x 32
    const dim3 grid_h(HH / 128, BB / 128);   // 8 x 32

    // gates: x@Wx^T + h@Ux^T (+biases), activations
    mma_gemm<2><<<grid_g, blk, SMEM_BYTES>>>(xh, xl, 1024, Wxh, Wxl, 1024, 32,
                                             hh, hl, 1024, Uxh, Uxl, 1024, 32,
                                             bWx, bUx, gates, nullptr, nullptr, NG);
    // alpha hidden: x@a1[:, :1024]^T + h@a1[:, 1024:]^T, relu
    mma_gemm<1><<<grid_h, blk, SMEM_BYTES>>>(xh, xl, 1024, a1h, a1l, 2048, 32,
                                             hh, hl, 1024, a1h + 1024, a1l + 1024, 2048, 32,
                                             a1_b, nullptr, ah, nullptr, nullptr, HH);
    alpha_kernel<<<BB, blk>>>(ah, a2_w, a2_b, alpha);
    // ssg_new = (ssg+h)@ssg_w^T + ssg_b  -> out_ssg (fp32)
    mma_gemm<0><<<grid_h, blk, SMEM_BYTES>>>(sgh, sgl, 1024, swh, swl, 1024, 32,
                                             nullptr, nullptr, 0, nullptr, nullptr, 0, 0,
                                             ssg_b, nullptr, out_ssg, nullptr, nullptr, HH);
    // r1 = relu(h@r1_w^T + b) -> bf16 pair
    mma_gemm<4><<<grid_h, blk, SMEM_BYTES>>>(hh, hl, 1024, w1h, w1l, 1024, 32,
                                             nullptr, nullptr, 0, nullptr, nullptr, 0, 0,
                                             r1_b, nullptr, nullptr, r1h, r1l, HH);
    // r2 = relu(r1@r2_w^T + b) -> bf16 pair
    mma_gemm<4><<<grid_h, blk, SMEM_BYTES>>>(r1h, r1l, 1024, w2h, w2l, 1024, 32,
                                             nullptr, nullptr, 0, nullptr, nullptr, 0, 0,
                                             r2_b, nullptr, nullptr, r2h, r2l, HH);
    // residual = r2@r3_w^T + b -> fp32
    mma_gemm<0><<<grid_h, blk, SMEM_BYTES>>>(r2h, r2l, 1024, w3h, w3l, 1024, 32,
                                             nullptr, nullptr, 0, nullptr, nullptr, 0, 0,
                                             r3_b, nullptr, res, nullptr, nullptr, HH);
    // fused cell update
    final_cell<<<BH / 4 / 256, blk>>>(gates, c_prev, alpha, out_ssg, res, out_h, out_c);
}